// round 7
// baseline (speedup 1.0000x reference)
#include <cuda_runtime.h>

// EquivariantLayerNorm, specialized to IRREPS=[(256,0),(128,1),(64,2),(32,3)]
//   dim = 1184, f4-per-row = 296
//   group f4 ranges: g0 [0,64) g1 [64,160) g2 [160,240) g3 [240,296)
//   group element counts: 256, 384, 320, 224
//   scalar block = g0 = columns [0,256); scalar_indices is identity there.
// Persistent kernel; branch-free 3-slot shuffle reduction; final combine
// split across threads 0..3 (independent short chains inside warp 0).

#define DIM   1184
#define NF4   296
#define EPSV  1e-5f

__global__ __launch_bounds__(256) void eln_kernel(const float* __restrict__ x,
                                                  float* __restrict__ out,
                                                  const float* __restrict__ weight,
                                                  const float* __restrict__ bias,
                                                  const int* __restrict__ irrep_idx,
                                                  int nrows) {
    const int t = threadIdx.x;
    const bool has1   = (t < NF4 - 256);      // t < 40: also owns f4 index t+256 (group 3 tail)
    const bool inPrim = (t < 240);            // false only for warp7 lanes 16-31 (g3)

    // ---- one-time init: per-column weight / bias into registers ----
    const int c0 = 4 * t;
    float4 w0, b0 = make_float4(0.f, 0.f, 0.f, 0.f);
    w0.x = weight[irrep_idx[c0 + 0]];
    w0.y = weight[irrep_idx[c0 + 1]];
    w0.z = weight[irrep_idx[c0 + 2]];
    w0.w = weight[irrep_idx[c0 + 3]];
    if (t < 64) {                             // scalar block: bias identity map
        b0.x = bias[c0 + 0];
        b0.y = bias[c0 + 1];
        b0.z = bias[c0 + 2];
        b0.w = bias[c0 + 3];
    }
    float4 w1 = make_float4(0.f, 0.f, 0.f, 0.f);
    if (has1) {
        const int c1 = c0 + 1024;
        w1.x = weight[irrep_idx[c1 + 0]];
        w1.y = weight[irrep_idx[c1 + 1]];
        w1.z = weight[irrep_idx[c1 + 2]];
        w1.w = weight[irrep_idx[c1 + 3]];
    }

    __shared__ float red[8][3];   // per-warp {slotA, slotB, slotC}
    __shared__ float bc[5];       // {smean, rn0, rn1, rn2, rn3}
    const int warp = t >> 5, lane = t & 31;

    int row = blockIdx.x;
    const int stride = gridDim.x;

    float4 v0 = make_float4(0.f, 0.f, 0.f, 0.f);
    float4 v1 = make_float4(0.f, 0.f, 0.f, 0.f);
    if (row < nrows) {
        const float4* xr = (const float4*)(x + (size_t)row * DIM);
        v0 = xr[t];
        if (has1) v1 = xr[t + 256];
    }

    while (row < nrows) {
        const float q0 = v0.x*v0.x + v0.y*v0.y + v0.z*v0.z + v0.w*v0.w;
        const float q1 = v1.x*v1.x + v1.y*v1.y + v1.z*v1.z + v1.w*v1.w;

        float sA = inPrim   ? q0 : 0.f;
        float sB = inPrim   ? q1 : q0;
        float sC = (t < 64) ? (v0.x + v0.y + v0.z + v0.w) : 0.f;

        // Prefetch next row while the reduction + barriers run.
        const int nrow = row + stride;
        float4 nv0 = make_float4(0.f, 0.f, 0.f, 0.f);
        float4 nv1 = make_float4(0.f, 0.f, 0.f, 0.f);
        if (nrow < nrows) {
            const float4* nxr = (const float4*)(x + (size_t)nrow * DIM);
            nv0 = nxr[t];
            if (has1) nv1 = nxr[t + 256];
        }

        #pragma unroll
        for (int off = 16; off; off >>= 1) {
            sA += __shfl_xor_sync(0xffffffffu, sA, off);
            sB += __shfl_xor_sync(0xffffffffu, sB, off);
            sC += __shfl_xor_sync(0xffffffffu, sC, off);
        }

        if (lane == 0) {
            red[warp][0] = sA;
            red[warp][1] = sB;
            red[warp][2] = sC;
        }
        __syncthreads();
        // Final combine split across threads 0..3: independent short chains,
        // all inside warp 0 so the four rsqrtf's run concurrently.
        if (t == 0) {
            float as = 0.f;
            #pragma unroll
            for (int w = 0; w < 8; w++) as += red[w][2];
            const float a0 = red[0][0] + red[1][0];                 // g0 sum-sq
            const float smean = as * (1.f / 256.f);
            bc[0] = smean;
            bc[1] = rsqrtf(a0 * (1.f / 256.f) - smean * smean + EPSV);
        } else if (t == 1) {
            const float a1 = red[2][0] + red[3][0] + red[4][0];     // g1 sum-sq
            bc[2] = rsqrtf(a1 * (1.f / 384.f) + EPSV);
        } else if (t == 2) {
            const float a2 = red[5][0] + red[6][0] + red[7][0];     // g2 sum-sq
            bc[3] = rsqrtf(a2 * (1.f / 320.f) + EPSV);
        } else if (t == 3) {
            float a3 = 0.f;                                          // g3 sum-sq
            #pragma unroll
            for (int w = 0; w < 8; w++) a3 += red[w][1];
            bc[4] = rsqrtf(a3 * (1.f / 224.f) + EPSV);
        }
        __syncthreads();

        const float smean = bc[0];
        float rn, sub0 = 0.f;
        if (t < 64)       { rn = bc[1]; sub0 = smean; }
        else if (t < 160) { rn = bc[2]; }
        else if (t < 240) { rn = bc[3]; }
        else              { rn = bc[4]; }
        const float rn3 = bc[4];

        float4* orow = (float4*)(out + (size_t)row * DIM);
        {
            float4 o;
            o.x = (v0.x - sub0) * rn * w0.x + b0.x;
            o.y = (v0.y - sub0) * rn * w0.y + b0.y;
            o.z = (v0.z - sub0) * rn * w0.z + b0.z;
            o.w = (v0.w - sub0) * rn * w0.w + b0.w;
            orow[t] = o;
        }
        if (has1) {
            float4 o;
            o.x = v1.x * rn3 * w1.x;
            o.y = v1.y * rn3 * w1.y;
            o.z = v1.z * rn3 * w1.z;
            o.w = v1.w * rn3 * w1.w;
            orow[t + 256] = o;
        }

        v0 = nv0;
        v1 = nv1;
        row = nrow;
    }
}

extern "C" void kernel_launch(void* const* d_in, const int* in_sizes, int n_in,
                              void* d_out, int out_size) {
    const float* x         = (const float*)d_in[0];
    const float* weight    = (const float*)d_in[1];
    const float* bias      = (const float*)d_in[2];
    const int*   irrep_idx = (const int*)  d_in[4];

    const int dim = in_sizes[3];           // 1184
    const int n   = in_sizes[0] / dim;     // 65536 rows

    const int grid = 148 * 4;              // persistent: ~111 rows per CTA
    eln_kernel<<<grid, 256>>>(x, (float*)d_out, weight, bias, irrep_idx, n);
}

// round 8
// speedup vs baseline: 1.9079x; 1.9079x over previous
#include <cuda_runtime.h>

// EquivariantLayerNorm, specialized to IRREPS=[(256,0),(128,1),(64,2),(32,3)]
//   dim = 1184, f4-per-row = 296
//   f4 group ranges: g0 [0,64) g1 [64,160) g2 [160,240) g3 [240,296)
//   element counts: 256, 384, 320, 224; scalar block = g0, identity bias map.
//
// Barrier-free design: CTA = 128 threads = 4 warps, one warp per group.
// Each warp owns up to 3 f4 slots per lane (i0, i0+32, i0+64 with validity),
// reduces its own group's stats with warp shuffles (butterfly -> all lanes
// hold the sum), computes rsqrt locally, scales and stores. No smem, no
// __syncthreads anywhere; warps free-run over rows.

#define DIM   1184
#define EPSV  1e-5f

__global__ __launch_bounds__(128) void eln_kernel(const float* __restrict__ x,
                                                  float* __restrict__ out,
                                                  const float* __restrict__ weight,
                                                  const float* __restrict__ bias,
                                                  const int* __restrict__ irrep_idx,
                                                  int nrows) {
    const int t    = threadIdx.x;
    const int warp = t >> 5;
    const int lane = t & 31;

    // ---- per-warp group parameters (init only; warp-uniform) ----
    int s0, sz; float inv;
    if (warp == 0)      { s0 = 0;   sz = 64; inv = 1.f / 256.f; }
    else if (warp == 1) { s0 = 64;  sz = 96; inv = 1.f / 384.f; }
    else if (warp == 2) { s0 = 160; sz = 80; inv = 1.f / 320.f; }
    else                { s0 = 240; sz = 56; inv = 1.f / 224.f; }
    const bool isScalar = (warp == 0);

    const int  i0 = s0 + lane;                 // always valid
    const bool p1 = (lane + 32) < sz;
    const bool p2 = (lane + 64) < sz;
    const int  i1 = i0 + 32;
    const int  i2 = i0 + 64;

    // ---- one-time init: per-slot weight / bias in registers ----
    float4 w0 = make_float4(0.f,0.f,0.f,0.f), w1 = w0, w2 = w0;
    {
        const int c = 4 * i0;
        w0.x = weight[irrep_idx[c+0]]; w0.y = weight[irrep_idx[c+1]];
        w0.z = weight[irrep_idx[c+2]]; w0.w = weight[irrep_idx[c+3]];
    }
    if (p1) {
        const int c = 4 * i1;
        w1.x = weight[irrep_idx[c+0]]; w1.y = weight[irrep_idx[c+1]];
        w1.z = weight[irrep_idx[c+2]]; w1.w = weight[irrep_idx[c+3]];
    }
    if (p2) {
        const int c = 4 * i2;
        w2.x = weight[irrep_idx[c+0]]; w2.y = weight[irrep_idx[c+1]];
        w2.z = weight[irrep_idx[c+2]]; w2.w = weight[irrep_idx[c+3]];
    }
    float4 b0 = make_float4(0.f,0.f,0.f,0.f), b1 = b0;
    if (isScalar) {   // scalar block = cols [0,256) = warp 0's two slots, identity map
        b0 = ((const float4*)bias)[i0];
        b1 = ((const float4*)bias)[i1];
    }

    int row = blockIdx.x;
    const int stride = gridDim.x;

    float4 v0 = make_float4(0.f,0.f,0.f,0.f), v1 = v0, v2 = v0;
    if (row < nrows) {
        const float4* xr = (const float4*)(x + (size_t)row * DIM);
        v0 = xr[i0];
        if (p1) v1 = xr[i1];
        if (p2) v2 = xr[i2];
    }

    while (row < nrows) {
        float q = v0.x*v0.x + v0.y*v0.y + v0.z*v0.z + v0.w*v0.w
                + v1.x*v1.x + v1.y*v1.y + v1.z*v1.z + v1.w*v1.w
                + v2.x*v2.x + v2.y*v2.y + v2.z*v2.z + v2.w*v2.w;
        float s = isScalar ? (v0.x + v0.y + v0.z + v0.w +
                              v1.x + v1.y + v1.z + v1.w) : 0.f;

        // Prefetch next row while the shuffles run.
        const int nrow = row + stride;
        float4 nv0 = make_float4(0.f,0.f,0.f,0.f), nv1 = nv0, nv2 = nv0;
        if (nrow < nrows) {
            const float4* nxr = (const float4*)(x + (size_t)nrow * DIM);
            nv0 = nxr[i0];
            if (p1) nv1 = nxr[i1];
            if (p2) nv2 = nxr[i2];
        }

        #pragma unroll
        for (int off = 16; off; off >>= 1) {
            q += __shfl_xor_sync(0xffffffffu, q, off);
            s += __shfl_xor_sync(0xffffffffu, s, off);
        }

        const float m  = s * inv;                       // 0 for non-scalar warps
        const float rn = rsqrtf(q * inv - m * m + EPSV);

        float4* orow = (float4*)(out + (size_t)row * DIM);
        {
            float4 o;
            o.x = (v0.x - m) * rn * w0.x + b0.x;
            o.y = (v0.y - m) * rn * w0.y + b0.y;
            o.z = (v0.z - m) * rn * w0.z + b0.z;
            o.w = (v0.w - m) * rn * w0.w + b0.w;
            orow[i0] = o;
        }
        if (p1) {
            float4 o;
            o.x = (v1.x - m) * rn * w1.x + b1.x;
            o.y = (v1.y - m) * rn * w1.y + b1.y;
            o.z = (v1.z - m) * rn * w1.z + b1.z;
            o.w = (v1.w - m) * rn * w1.w + b1.w;
            orow[i1] = o;
        }
        if (p2) {
            float4 o;
            o.x = v2.x * rn * w2.x;                     // slot2 never scalar: m=0, b=0
            o.y = v2.y * rn * w2.y;
            o.z = v2.z * rn * w2.z;
            o.w = v2.w * rn * w2.w;
            orow[i2] = o;
        }

        v0 = nv0; v1 = nv1; v2 = nv2;
        row = nrow;
    }
}

extern "C" void kernel_launch(void* const* d_in, const int* in_sizes, int n_in,
                              void* d_out, int out_size) {
    const float* x         = (const float*)d_in[0];
    const float* weight    = (const float*)d_in[1];
    const float* bias      = (const float*)d_in[2];
    const int*   irrep_idx = (const int*)  d_in[4];

    const int dim = in_sizes[3];           // 1184
    const int n   = in_sizes[0] / dim;     // 65536 rows

    const int grid = 148 * 8;              // persistent: ~55 rows per CTA
    eln_kernel<<<grid, 128>>>(x, (float*)d_out, weight, bias, irrep_idx, n);
}